// round 14
// baseline (speedup 1.0000x reference)
#include <cuda_runtime.h>

#define NUM_FEATURES 10
#define EMBED 256
#define MAXLEN 366
#define PE_ROWS (MAXLEN + 1)
#define OUT_DIM (2 * EMBED)
#define BLOCKS_PER_SM 3
#define GRID (148 * BLOCKS_PER_SM)                 // 444 blocks, single wave
#define NTOK 131072                                // 256 x 512 fixed shape
#define TOK_PER_BLOCK ((NTOK + GRID - 1) / GRID)   // 296, compile-time
#define SDOY_PAD 8

// ---------------------------------------------------------------------------
// Compile-time PE table: row 0 zeros, rows 1..366 = sin/cos(pos * div_i),
// baked into the cubin. Single launch node, no fill kernel.
// ---------------------------------------------------------------------------
constexpr double c_sin_poly(double x) {
    double x2 = x * x, term = x, sum = x;
    for (int n = 1; n <= 10; n++) { term *= -x2 / ((2.0 * n) * (2.0 * n + 1.0)); sum += term; }
    return sum;
}
constexpr double c_cos_poly(double x) {
    double x2 = x * x, term = 1.0, sum = 1.0;
    for (int n = 1; n <= 10; n++) { term *= -x2 / ((2.0 * n - 1.0) * (2.0 * n)); sum += term; }
    return sum;
}
constexpr double c_exp(double x) {
    double r = x / 16.0, term = 1.0, sum = 1.0;
    for (int n = 1; n <= 14; n++) { term *= r / (double)n; sum += term; }
    for (int k = 0; k < 4; k++) sum *= sum;
    return sum;
}

struct PETable { alignas(16) float v[PE_ROWS * EMBED]; };

constexpr PETable make_pe() {
    PETable t{};
    constexpr double LOG1E4 = 9.21034037197618273607196896;
    for (int i = 0; i < EMBED / 2; i++) {
        double div = c_exp(-(double)(2 * i) * (LOG1E4 / (double)EMBED));
        double sd = c_sin_poly(div), cd = c_cos_poly(div);
        double s = 0.0, c = 1.0;
        for (int p = 0; p < MAXLEN; p++) {
            t.v[(p + 1) * EMBED + 2 * i]     = (float)s;
            t.v[(p + 1) * EMBED + 2 * i + 1] = (float)c;
            double s2 = s * cd + c * sd;
            double c2 = c * cd - s * sd;
            s = s2; c = c2;
        }
    }
    return t;
}

__device__ constexpr PETable g_pe_tab = make_pe();

// ---------------------------------------------------------------------------
// Packed f32x2 helpers.
// ---------------------------------------------------------------------------
__device__ __forceinline__ unsigned long long pack2(float a, float b) {
    unsigned long long r;
    asm("mov.b64 %0, {%1, %2};" : "=l"(r) : "f"(a), "f"(b));
    return r;
}
__device__ __forceinline__ unsigned long long fma2(unsigned long long a,
                                                   unsigned long long b,
                                                   unsigned long long c) {
    unsigned long long d;
    asm("fma.rn.f32x2 %0, %1, %2, %3;" : "=l"(d) : "l"(a), "l"(b), "l"(c));
    return d;
}

// ---------------------------------------------------------------------------
// Main kernel -- 4 channels/thread, channel-paired packed math.
// Mapping: e_lane = tid & 63 owns channels e0..e0+3 (e0 = e_lane*4);
// t_lane = tid >> 6 in {0..3} gives 4 token lanes. Per token only 2 warps
// work (vs 4 in the R13 layout) -> ~37% fewer warp-instructions per token.
// x is staged DUPLICATED ({v,v}) so each feature feeds both channel-pair
// FMAs without splat; per token: 1 sdoy LDS, 5 LDS.128, 1 LDG.128 gather
// (software-pipelined 1 iter ahead), 20 fma2, 2 STG.128. sdoy is padded so
// the prefetch needs no bounds select. ~78 regs -> 3 blocks/SM, 24 warps.
// ---------------------------------------------------------------------------
__global__ __launch_bounds__(256, BLOCKS_PER_SM)
void bert_embed_kernel(const float* __restrict__ x,     // [NTOK, 10]
                       const int*   __restrict__ doy,   // [NTOK]
                       const float* __restrict__ W,     // [256, 10]
                       const float* __restrict__ bias_g,// [256]
                       float*       __restrict__ out)   // [NTOK, 512]
{
    __shared__ __align__(16) float2 sx2[TOK_PER_BLOCK * NUM_FEATURES]; // {v,v}
    __shared__ int sdoy[TOK_PER_BLOCK + SDOY_PAD];

    const float* __restrict__ pe = g_pe_tab.v;

    const int t0  = blockIdx.x * TOK_PER_BLOCK;
    const int cnt = min(TOK_PER_BLOCK, NTOK - t0);
    if (cnt <= 0) return;

    // Stage x duplicated + doy (coalesced LDG). Pad sdoy tail with zeros so
    // the pipelined prefetch can index past cnt without a select.
    for (int i = threadIdx.x; i < cnt * NUM_FEATURES; i += 256) {
        float v = __ldg(x + (size_t)t0 * NUM_FEATURES + i);
        sx2[i] = make_float2(v, v);
    }
    for (int i = threadIdx.x; i < cnt + SDOY_PAD; i += 256)
        sdoy[i] = (i < cnt) ? __ldg(doy + t0 + i) : 0;

    const int e_lane = threadIdx.x & 63;
    const int t_lane = threadIdx.x >> 6;           // 0..3
    const int e0 = e_lane * 4;

    // Channel-paired packed weights: wp01[f]=(W[e0][f],W[e0+1][f]),
    // wp23[f]=(W[e0+2][f],W[e0+3][f]). 20 b64 regs.
    unsigned long long wp01[NUM_FEATURES], wp23[NUM_FEATURES];
#pragma unroll
    for (int f = 0; f < NUM_FEATURES; f++) {
        wp01[f] = pack2(__ldg(W + (e0 + 0) * NUM_FEATURES + f),
                        __ldg(W + (e0 + 1) * NUM_FEATURES + f));
        wp23[f] = pack2(__ldg(W + (e0 + 2) * NUM_FEATURES + f),
                        __ldg(W + (e0 + 3) * NUM_FEATURES + f));
    }
    const unsigned long long b01 = pack2(__ldg(bias_g + e0),     __ldg(bias_g + e0 + 1));
    const unsigned long long b23 = pack2(__ldg(bias_g + e0 + 2), __ldg(bias_g + e0 + 3));

    __syncthreads();

    int tt = t_lane;
    float* op = out + (size_t)(t0 + t_lane) * OUT_DIM + e0;

    // Prologue gather (padded sdoy -> safe even when t_lane >= cnt, since
    // row 0 of the table is all zeros and the loop below won't store it).
    float4 pev = *reinterpret_cast<const float4*>(&pe[sdoy[min(tt, cnt + 3)] * EMBED + e0]);

    for (; tt < cnt; tt += 4, op += 4 * OUT_DIM) {
        // Prefetch next iteration's PE row (padded: no bounds select).
        const int dn = sdoy[tt + 4];
        const float4 pev_next =
            *reinterpret_cast<const float4*>(&pe[dn * EMBED + e0]);

        // x features: 5 broadcast LDS.128 of duplicated pairs.
        const ulonglong2* xp =
            reinterpret_cast<const ulonglong2*>(sx2 + tt * NUM_FEATURES);
        ulonglong2 x0 = xp[0], x1 = xp[1], x2 = xp[2], x3 = xp[3], x4 = xp[4];

        unsigned long long a01 = b01, a23 = b23;
        a01 = fma2(x0.x, wp01[0], a01); a23 = fma2(x0.x, wp23[0], a23);
        a01 = fma2(x0.y, wp01[1], a01); a23 = fma2(x0.y, wp23[1], a23);
        a01 = fma2(x1.x, wp01[2], a01); a23 = fma2(x1.x, wp23[2], a23);
        a01 = fma2(x1.y, wp01[3], a01); a23 = fma2(x1.y, wp23[3], a23);
        a01 = fma2(x2.x, wp01[4], a01); a23 = fma2(x2.x, wp23[4], a23);
        a01 = fma2(x2.y, wp01[5], a01); a23 = fma2(x2.y, wp23[5], a23);
        a01 = fma2(x3.x, wp01[6], a01); a23 = fma2(x3.x, wp23[6], a23);
        a01 = fma2(x3.y, wp01[7], a01); a23 = fma2(x3.y, wp23[7], a23);
        a01 = fma2(x4.x, wp01[8], a01); a23 = fma2(x4.x, wp23[8], a23);
        a01 = fma2(x4.y, wp01[9], a01); a23 = fma2(x4.y, wp23[9], a23);

        ulonglong2 obs; obs.x = a01; obs.y = a23;   // (ch0,ch1,ch2,ch3) packed
        __stcs(reinterpret_cast<ulonglong2*>(op), obs);
        __stcs(reinterpret_cast<float4*>(op + EMBED), pev);

        pev = pev_next;
    }
}

extern "C" void kernel_launch(void* const* d_in, const int* in_sizes, int n_in,
                              void* d_out, int out_size) {
    const float* x    = (const float*)d_in[0];   // input_sequence [256,512,10]
    const int*   doy  = (const int*)  d_in[1];   // doy_sequence   [256,512]
    const float* W    = (const float*)d_in[2];   // [256,10]
    const float* b    = (const float*)d_in[3];   // [256]
    float*       out  = (float*)d_out;           // [256,512,512]

    // Single kernel node: PE table is baked into the module image.
    bert_embed_kernel<<<GRID, 256>>>(x, doy, W, b, out);
}

// round 15
// speedup vs baseline: 1.0491x; 1.0491x over previous
#include <cuda_runtime.h>

#define NUM_FEATURES 10
#define XSTRIDE 12               // padded x row stride (floats), 16B-aligned rows
#define EMBED 256
#define MAXLEN 366
#define PE_ROWS (MAXLEN + 1)
#define OUT_DIM (2 * EMBED)
#define GRID 740                 // 148 SMs x 5 resident blocks, single wave
#define NTOK 131072              // 256 x 512 (fixed problem shape)
#define TOK_PER_BLOCK ((NTOK + GRID - 1) / GRID)   // 178, compile-time
#define SDOY_PAD 8

// ---------------------------------------------------------------------------
// Compile-time PE table: row 0 zeros, rows 1..366 = sin/cos(pos * div_i),
// baked into the cubin. Single launch node, no fill kernel.
// ---------------------------------------------------------------------------
constexpr double c_sin_poly(double x) {            // |x| <= 1
    double x2 = x * x, term = x, sum = x;
    for (int n = 1; n <= 10; n++) { term *= -x2 / ((2.0 * n) * (2.0 * n + 1.0)); sum += term; }
    return sum;
}
constexpr double c_cos_poly(double x) {            // |x| <= 1
    double x2 = x * x, term = 1.0, sum = 1.0;
    for (int n = 1; n <= 10; n++) { term *= -x2 / ((2.0 * n - 1.0) * (2.0 * n)); sum += term; }
    return sum;
}
constexpr double c_exp(double x) {                 // x in [-9.22, 0]
    double r = x / 16.0, term = 1.0, sum = 1.0;
    for (int n = 1; n <= 14; n++) { term *= r / (double)n; sum += term; }
    for (int k = 0; k < 4; k++) sum *= sum;        // ^16
    return sum;
}

struct PETable { alignas(16) float v[PE_ROWS * EMBED]; };

constexpr PETable make_pe() {
    PETable t{};                                   // row 0 zero-initialized
    constexpr double LOG1E4 = 9.21034037197618273607196896;  // ln(10000)
    for (int i = 0; i < EMBED / 2; i++) {
        double div = c_exp(-(double)(2 * i) * (LOG1E4 / (double)EMBED));
        double sd = c_sin_poly(div), cd = c_cos_poly(div);
        double s = 0.0, c = 1.0;                   // angle = 0 at pos 0
        for (int p = 0; p < MAXLEN; p++) {
            t.v[(p + 1) * EMBED + 2 * i]     = (float)s;
            t.v[(p + 1) * EMBED + 2 * i + 1] = (float)c;
            double s2 = s * cd + c * sd;           // rotate by div
            double c2 = c * cd - s * sd;
            s = s2; c = c2;
        }
    }
    return t;
}

__device__ constexpr PETable g_pe_tab = make_pe();

// ---------------------------------------------------------------------------
// Packed f32x2 helpers (sm_103a dual FMA; PTX-only, ptxas won't auto-fuse).
// ---------------------------------------------------------------------------
__device__ __forceinline__ unsigned long long pack2(float a, float b) {
    unsigned long long r;
    asm("mov.b64 %0, {%1, %2};" : "=l"(r) : "f"(a), "f"(b));
    return r;
}
__device__ __forceinline__ unsigned long long fma2(unsigned long long a,
                                                   unsigned long long b,
                                                   unsigned long long c) {
    unsigned long long d;
    asm("fma.rn.f32x2 %0, %1, %2, %3;" : "=l"(d) : "l"(a), "l"(b), "l"(c));
    return d;
}
__device__ __forceinline__ float2 unpack2(unsigned long long v) {
    float lo, hi;
    asm("mov.b64 {%0, %1}, %2;" : "=f"(lo), "=f"(hi) : "l"(v));
    return make_float2(lo, hi);
}

// ---------------------------------------------------------------------------
// Main kernel -- R13 shape (48 regs, 5 blocks/SM, 40 warps: the measured
// equilibrium point; fewer warps loses DRAM%, more needs <=51 regs) with the
// per-iteration bookkeeping stripped further:
//  * sdoy padded with zeros -> prefetch index needs NO bounds select
//  * smem x pointer advances by constant (LDS with immediate offsets)
//  * store pointer advances by constant (STG with immediate offsets)
//  * pre-packed bias constants hoisted out of the loop
// ---------------------------------------------------------------------------
__global__ __launch_bounds__(256, 5)
void bert_embed_kernel(const float* __restrict__ x,     // [NTOK, 10]
                       const int*   __restrict__ doy,   // [NTOK]
                       const float* __restrict__ W,     // [256, 10]
                       const float* __restrict__ bias_g,// [256]
                       float*       __restrict__ out)   // [NTOK, 512]
{
    __shared__ __align__(16) float sx[TOK_PER_BLOCK * XSTRIDE];
    __shared__ int sdoy[TOK_PER_BLOCK + SDOY_PAD];

    const float* __restrict__ pe = g_pe_tab.v;

    const int t0  = blockIdx.x * TOK_PER_BLOCK;
    const int cnt = min(TOK_PER_BLOCK, NTOK - t0);
    if (cnt <= 0) return;

    // Stage x into stride-12 rows + doy (coalesced LDG). Zero-pad sdoy tail
    // so the pipelined prefetch can index past cnt without a select.
    for (int i = threadIdx.x; i < cnt * NUM_FEATURES; i += 256) {
        int row = i / NUM_FEATURES;
        int col = i - row * NUM_FEATURES;
        sx[row * XSTRIDE + col] = __ldg(x + (size_t)t0 * NUM_FEATURES + i);
    }
    for (int i = threadIdx.x; i < cnt + SDOY_PAD; i += 256)
        sdoy[i] = (i < cnt) ? __ldg(doy + t0 + i) : 0;

    const int e_lane = threadIdx.x & 127;
    const int t_lane = threadIdx.x >> 7;           // 0 or 1
    const int e0 = e_lane * 2;

    // Feature-pair-packed weights for this thread's 2 channels (10 b64 regs).
    unsigned long long wp0[5], wp1[5];
#pragma unroll
    for (int p = 0; p < 5; p++) {
        wp0[p] = pack2(__ldg(W + (e0 + 0) * NUM_FEATURES + 2 * p),
                       __ldg(W + (e0 + 0) * NUM_FEATURES + 2 * p + 1));
        wp1[p] = pack2(__ldg(W + (e0 + 1) * NUM_FEATURES + 2 * p),
                       __ldg(W + (e0 + 1) * NUM_FEATURES + 2 * p + 1));
    }
    // Pre-packed bias accumulator seeds (hoisted -- no per-iter pack).
    const unsigned long long b0p = pack2(__ldg(bias_g + e0),     0.0f);
    const unsigned long long b1p = pack2(__ldg(bias_g + e0 + 1), 0.0f);

    __syncthreads();

    int tt = t_lane;
    // Pointer recurrences: constant strides, memory ops use immediate offsets.
    const float* xr = sx + t_lane * XSTRIDE;
    float*       op = out + (size_t)(t0 + t_lane) * OUT_DIM + e0;

    // Prologue gather (sdoy is padded and zero rows are harmless).
    float2 pev = *reinterpret_cast<const float2*>(&pe[sdoy[tt] * EMBED + e0]);

    for (; tt < cnt; tt += 2, xr += 2 * XSTRIDE, op += 2 * OUT_DIM) {
        // Prefetch next iteration's PE row (padded sdoy: no bounds select).
        const int dn = sdoy[tt + 2];
        const float2 pev_next =
            *reinterpret_cast<const float2*>(&pe[dn * EMBED + e0]);

        // x features: 3 broadcast shared loads at immediate offsets.
        float4 q0 = *reinterpret_cast<const float4*>(xr);
        float4 q1 = *reinterpret_cast<const float4*>(xr + 4);
        float2 q2 = *reinterpret_cast<const float2*>(xr + 8);

        unsigned long long a0 = b0p, a1 = b1p;

        unsigned long long xx;
        xx = pack2(q0.x, q0.y); a0 = fma2(xx, wp0[0], a0); a1 = fma2(xx, wp1[0], a1);
        xx = pack2(q0.z, q0.w); a0 = fma2(xx, wp0[1], a0); a1 = fma2(xx, wp1[1], a1);
        xx = pack2(q1.x, q1.y); a0 = fma2(xx, wp0[2], a0); a1 = fma2(xx, wp1[2], a1);
        xx = pack2(q1.z, q1.w); a0 = fma2(xx, wp0[3], a0); a1 = fma2(xx, wp1[3], a1);
        xx = pack2(q2.x, q2.y); a0 = fma2(xx, wp0[4], a0); a1 = fma2(xx, wp1[4], a1);

        float2 r0 = unpack2(a0);
        float2 r1 = unpack2(a1);

        __stcs(reinterpret_cast<float2*>(op),
               make_float2(r0.x + r0.y, r1.x + r1.y));
        __stcs(reinterpret_cast<float2*>(op + EMBED), pev);

        pev = pev_next;
    }
}

extern "C" void kernel_launch(void* const* d_in, const int* in_sizes, int n_in,
                              void* d_out, int out_size) {
    const float* x    = (const float*)d_in[0];   // input_sequence [256,512,10]
    const int*   doy  = (const int*)  d_in[1];   // doy_sequence   [256,512]
    const float* W    = (const float*)d_in[2];   // [256,10]
    const float* b    = (const float*)d_in[3];   // [256]
    float*       out  = (float*)d_out;           // [256,512,512]

    // Single kernel node: PE table is baked into the module image.
    bert_embed_kernel<<<GRID, 256>>>(x, doy, W, b, out);
}

// round 16
// speedup vs baseline: 1.0615x; 1.0118x over previous
#include <cuda_runtime.h>

#define NUM_FEATURES 10
#define XSTRIDE 12               // padded x row stride (floats), 16B-aligned rows
#define EMBED 256
#define MAXLEN 366
#define PE_ROWS (MAXLEN + 1)
#define OUT_DIM (2 * EMBED)
#define GRID 740                 // 148 SMs x 5 resident blocks, single wave
#define NTOK 131072              // 256 x 512 (fixed problem shape)
#define TOK_PER_BLOCK ((NTOK + GRID - 1) / GRID)   // 178, compile-time

// ---------------------------------------------------------------------------
// Compile-time PE table: row 0 zeros, rows 1..366 = sin/cos(pos * div_i),
// div_i = 10000^(-2i/256). Built entirely at compile time (Taylor exp/sin/cos
// seeds + double-precision angle-addition recurrence) and baked into the
// cubin. No fill kernel, no PDL, single launch node.
// ---------------------------------------------------------------------------
constexpr double c_sin_poly(double x) {            // |x| <= 1
    double x2 = x * x, term = x, sum = x;
    for (int n = 1; n <= 10; n++) { term *= -x2 / ((2.0 * n) * (2.0 * n + 1.0)); sum += term; }
    return sum;
}
constexpr double c_cos_poly(double x) {            // |x| <= 1
    double x2 = x * x, term = 1.0, sum = 1.0;
    for (int n = 1; n <= 10; n++) { term *= -x2 / ((2.0 * n - 1.0) * (2.0 * n)); sum += term; }
    return sum;
}
constexpr double c_exp(double x) {                 // x in [-9.22, 0]
    double r = x / 16.0, term = 1.0, sum = 1.0;
    for (int n = 1; n <= 14; n++) { term *= r / (double)n; sum += term; }
    for (int k = 0; k < 4; k++) sum *= sum;        // ^16
    return sum;
}

struct PETable { alignas(16) float v[PE_ROWS * EMBED]; };

constexpr PETable make_pe() {
    PETable t{};                                   // row 0 zero-initialized
    constexpr double LOG1E4 = 9.21034037197618273607196896;  // ln(10000)
    for (int i = 0; i < EMBED / 2; i++) {
        double div = c_exp(-(double)(2 * i) * (LOG1E4 / (double)EMBED));
        double sd = c_sin_poly(div), cd = c_cos_poly(div);
        double s = 0.0, c = 1.0;                   // angle = 0 at pos 0
        for (int p = 0; p < MAXLEN; p++) {
            t.v[(p + 1) * EMBED + 2 * i]     = (float)s;
            t.v[(p + 1) * EMBED + 2 * i + 1] = (float)c;
            double s2 = s * cd + c * sd;           // rotate by div
            double c2 = c * cd - s * sd;
            s = s2; c = c2;
        }
    }
    return t;
}

__device__ constexpr PETable g_pe_tab = make_pe();

// ---------------------------------------------------------------------------
// Packed f32x2 helpers (sm_103a dual FMA; PTX-only, ptxas won't auto-fuse).
// ---------------------------------------------------------------------------
__device__ __forceinline__ unsigned long long pack2(float a, float b) {
    unsigned long long r;
    asm("mov.b64 %0, {%1, %2};" : "=l"(r) : "f"(a), "f"(b));
    return r;
}
__device__ __forceinline__ unsigned long long fma2(unsigned long long a,
                                                   unsigned long long b,
                                                   unsigned long long c) {
    unsigned long long d;
    asm("fma.rn.f32x2 %0, %1, %2, %3;" : "=l"(d) : "l"(a), "l"(b), "l"(c));
    return d;
}
__device__ __forceinline__ float2 unpack2(unsigned long long v) {
    float lo, hi;
    asm("mov.b64 {%0, %1}, %2;" : "=f"(lo), "=f"(hi) : "l"(v));
    return make_float2(lo, hi);
}

// ---------------------------------------------------------------------------
// Main kernel -- the measured-best configuration (R13: main 45.8us, total
// 47.58us). 48 regs natural size, 5 blocks/SM, 40 warps (the equilibrium
// point: fewer warps loses DRAM%, squeezing regs spills through L1).
// Feature-pair-packed f32x2 math, 3 broadcast LDS per token, sdoy staged in
// smem, software-pipelined PE gather, streaming float2 stores, compile-time
// TOK_PER_BLOCK, hoisted store pointer. R14 (4ch/thread) and R15 (further
// bookkeeping strip) both regressed -- this exact schedule is the keeper.
// ---------------------------------------------------------------------------
__global__ __launch_bounds__(256, 5)
void bert_embed_kernel(const float* __restrict__ x,     // [NTOK, 10]
                       const int*   __restrict__ doy,   // [NTOK]
                       const float* __restrict__ W,     // [256, 10]
                       const float* __restrict__ bias_g,// [256]
                       float*       __restrict__ out)   // [NTOK, 512]
{
    __shared__ __align__(16) float sx[TOK_PER_BLOCK * XSTRIDE];
    __shared__ int sdoy[TOK_PER_BLOCK];

    const float* __restrict__ pe = g_pe_tab.v;

    const int t0  = blockIdx.x * TOK_PER_BLOCK;
    const int cnt = min(TOK_PER_BLOCK, NTOK - t0);
    if (cnt <= 0) return;

    // Stage x into stride-12 rows + doy. Coalesced LDG.
    for (int i = threadIdx.x; i < cnt * NUM_FEATURES; i += 256) {
        int row = i / NUM_FEATURES;
        int col = i - row * NUM_FEATURES;
        sx[row * XSTRIDE + col] = __ldg(x + (size_t)t0 * NUM_FEATURES + i);
    }
    for (int i = threadIdx.x; i < cnt; i += 256)
        sdoy[i] = __ldg(doy + t0 + i);

    const int e_lane = threadIdx.x & 127;
    const int t_lane = threadIdx.x >> 7;           // 0 or 1
    const int e0 = e_lane * 2;

    // Feature-pair-packed weights for this thread's 2 channels (10 b64 regs).
    unsigned long long wp0[5], wp1[5];
#pragma unroll
    for (int p = 0; p < 5; p++) {
        wp0[p] = pack2(__ldg(W + (e0 + 0) * NUM_FEATURES + 2 * p),
                       __ldg(W + (e0 + 0) * NUM_FEATURES + 2 * p + 1));
        wp1[p] = pack2(__ldg(W + (e0 + 1) * NUM_FEATURES + 2 * p),
                       __ldg(W + (e0 + 1) * NUM_FEATURES + 2 * p + 1));
    }
    const float bias0 = __ldg(bias_g + e0);
    const float bias1 = __ldg(bias_g + e0 + 1);

    __syncthreads();

    int tt = t_lane;
    // Hoisted store pointer: advances by a constant 2*OUT_DIM per iteration.
    float* op = out + (size_t)(t0 + t_lane) * OUT_DIM + e0;

    float2 pev = make_float2(0.f, 0.f);
    if (tt < cnt)
        pev = *reinterpret_cast<const float2*>(&pe[sdoy[tt] * EMBED + e0]);

    for (; tt < cnt; tt += 2, op += 2 * OUT_DIM) {
        // Prefetch next iteration's gather (row 0 = zeros is a safe dummy).
        const int tn = tt + 2;
        const int dn = (tn < cnt) ? sdoy[tn] : 0;
        const float2 pev_next =
            *reinterpret_cast<const float2*>(&pe[dn * EMBED + e0]);

        // x features: 3 broadcast shared loads, consumed in place.
        const float* xr = sx + tt * XSTRIDE;
        float4 q0 = *reinterpret_cast<const float4*>(xr);
        float4 q1 = *reinterpret_cast<const float4*>(xr + 4);
        float2 q2 = *reinterpret_cast<const float2*>(xr + 8);

        unsigned long long a0 = pack2(bias0, 0.0f);
        unsigned long long a1 = pack2(bias1, 0.0f);

        unsigned long long xx;
        xx = pack2(q0.x, q0.y); a0 = fma2(xx, wp0[0], a0); a1 = fma2(xx, wp1[0], a1);
        xx = pack2(q0.z, q0.w); a0 = fma2(xx, wp0[1], a0); a1 = fma2(xx, wp1[1], a1);
        xx = pack2(q1.x, q1.y); a0 = fma2(xx, wp0[2], a0); a1 = fma2(xx, wp1[2], a1);
        xx = pack2(q1.z, q1.w); a0 = fma2(xx, wp0[3], a0); a1 = fma2(xx, wp1[3], a1);
        xx = pack2(q2.x, q2.y); a0 = fma2(xx, wp0[4], a0); a1 = fma2(xx, wp1[4], a1);

        float2 r0 = unpack2(a0);
        float2 r1 = unpack2(a1);

        __stcs(reinterpret_cast<float2*>(op),
               make_float2(r0.x + r0.y, r1.x + r1.y));
        __stcs(reinterpret_cast<float2*>(op + EMBED), pev);

        pev = pev_next;
    }
}

extern "C" void kernel_launch(void* const* d_in, const int* in_sizes, int n_in,
                              void* d_out, int out_size) {
    const float* x    = (const float*)d_in[0];   // input_sequence [256,512,10]
    const int*   doy  = (const int*)  d_in[1];   // doy_sequence   [256,512]
    const float* W    = (const float*)d_in[2];   // [256,10]
    const float* b    = (const float*)d_in[3];   // [256]
    float*       out  = (float*)d_out;           // [256,512,512]

    // Single kernel node: PE table is baked into the module image.
    bert_embed_kernel<<<GRID, 256>>>(x, doy, W, b, out);
}